// round 11
// baseline (speedup 1.0000x reference)
#include <cuda_runtime.h>

// ---------------------------------------------------------------------------
// BatchedGeometryComputation
//   out = [centroids (n_blocks*3) | rel (n_atoms*3) | dist (n_atoms) | rbf (n_atoms*16)]
// block_id is SORTED ascending.
// ---------------------------------------------------------------------------

#define RBF_DIM 16
#define MAX_BLOCKS_SCRATCH 262144
#define TPB 256
#define LOG2E 1.4426950408889634f

// scratch: per-block (sum_x, sum_y, sum_z, count)
__device__ float4 g_sums[MAX_BLOCKS_SCRATCH];

__global__ void k_zero_sums(int n_blocks) {
    for (int i = blockIdx.x * blockDim.x + threadIdx.x; i < n_blocks;
         i += gridDim.x * blockDim.x)
        g_sums[i] = make_float4(0.f, 0.f, 0.f, 0.f);
}

// One atom per lane; pos staged via float4 into shared (3 load wf/warp);
// warp-level segmented reduction over sorted ids; heads issue atomics.
__global__ void __launch_bounds__(TPB)
k_accum(const float* __restrict__ pos,
        const int* __restrict__ bid,
        int n_atoms) {
    __shared__ float s_p[3 * TPB];
    int t    = threadIdx.x;
    int lane = t & 31;
    int a0   = blockIdx.x * TPB;
    bool fullt = (a0 + TPB) <= n_atoms;

    if (fullt) {
        const float4* p4 = (const float4*)(pos + (size_t)3 * a0);
        if (t < (3 * TPB / 4)) ((float4*)s_p)[t] = p4[t];
    } else {
        for (int k = t; k < 3 * TPB; k += TPB) {
            int gi = 3 * a0 + k;
            s_p[k] = (gi < 3 * n_atoms) ? pos[gi] : 0.f;
        }
    }
    __syncthreads();

    int i = a0 + t;
    bool valid = i < n_atoms;
    int idx = valid ? i : (n_atoms - 1);

    int   b   = bid[idx];
    float sx  = valid ? s_p[3 * t + 0] : 0.f;
    float sy  = valid ? s_p[3 * t + 1] : 0.f;
    float sz  = valid ? s_p[3 * t + 2] : 0.f;
    float cnt = valid ? 1.f : 0.f;

#pragma unroll
    for (int off = 1; off < 32; off <<= 1) {
        int   ob = __shfl_down_sync(0xffffffffu, b, off);
        float ox = __shfl_down_sync(0xffffffffu, sx, off);
        float oy = __shfl_down_sync(0xffffffffu, sy, off);
        float oz = __shfl_down_sync(0xffffffffu, sz, off);
        float oc = __shfl_down_sync(0xffffffffu, cnt, off);
        if (lane + off < 32 && ob == b) {
            sx += ox; sy += oy; sz += oz; cnt += oc;
        }
    }

    int prev_b = __shfl_up_sync(0xffffffffu, b, 1);
    bool head = (lane == 0) || (prev_b != b);
    if (head && cnt > 0.f) {
        float* p = (float*)&g_sums[b];
        atomicAdd(p + 0, sx);
        atomicAdd(p + 1, sy);
        atomicAdd(p + 2, sz);
        atomicAdd(p + 3, cnt);
    }
}

// Per-atom kernel, transposed rbf stores, FMA-form exp args, fused centroid
// output (threads with gid < n_blocks also write out_cent from g_sums).
__global__ void __launch_bounds__(TPB, 6)
k_atoms(const float* __restrict__ pos,
        const int* __restrict__ bid,
        const float* __restrict__ centers,
        const float* __restrict__ widths,
        float* __restrict__ out_cent,
        float* __restrict__ out_rel,
        float* __restrict__ out_dist,
        float4* __restrict__ out_rbf,     // n_atoms * 4 float4
        int n_atoms, int n_blocks) {
    __shared__ float s_c[RBF_DIM];
    __shared__ float s_iw[RBF_DIM];
    __shared__ float s_xyz[3 * TPB];      // staged pos, then reused for rel

    int t    = threadIdx.x;
    int lane = t & 31;

    if (t < RBF_DIM) {
        s_c[t] = centers[t];
        float w = widths[t];
        s_iw[t] = 1.f / (2.f * w * w);
    }

    int a0 = blockIdx.x * TPB;            // first atom of this block
    bool fullt = (a0 + TPB) <= n_atoms;

    // ---- stage pos into shared ----
    if (fullt) {
        const float4* p4 = (const float4*)(pos + (size_t)3 * a0);
        if (t < (3 * TPB / 4)) ((float4*)s_xyz)[t] = p4[t];
    } else {
        for (int k = t; k < 3 * TPB; k += TPB) {
            int gi = 3 * a0 + k;
            s_xyz[k] = (gi < 3 * n_atoms) ? pos[gi] : 0.f;
        }
    }
    __syncthreads();

    // per-lane RBF constants in FMA form:
    //   exp(-(d-c)^2*iw) = exp2(A*d^2 + B*d + C)
    //   A = -iw*log2e,  B = 2c*iw*log2e,  C = -c^2*iw*log2e
    int q = lane & 3;
    float A0, A1, A2, A3, B0, B1, B2, B3, C0, C1, C2, C3;
    {
        float c, iw, il;
        c = s_c[4 * q + 0]; iw = s_iw[4 * q + 0]; il = iw * LOG2E;
        A0 = -il; B0 = 2.f * c * il; C0 = -c * c * il;
        c = s_c[4 * q + 1]; iw = s_iw[4 * q + 1]; il = iw * LOG2E;
        A1 = -il; B1 = 2.f * c * il; C1 = -c * c * il;
        c = s_c[4 * q + 2]; iw = s_iw[4 * q + 2]; il = iw * LOG2E;
        A2 = -il; B2 = 2.f * c * il; C2 = -c * c * il;
        c = s_c[4 * q + 3]; iw = s_iw[4 * q + 3]; il = iw * LOG2E;
        A3 = -il; B3 = 2.f * c * il; C3 = -c * c * il;
    }

    int i = a0 + t;
    bool act = i < n_atoms;
    float d = 0.f;

    if (act) {
        int b = bid[i];
        float4 s = g_sums[b];             // single LDG.128, broadcast-friendly
        float inv = 1.f / fmaxf(s.w, 1.f);

        float rx = s_xyz[3 * t + 0] - s.x * inv;
        float ry = s_xyz[3 * t + 1] - s.y * inv;
        float rz = s_xyz[3 * t + 2] - s.z * inv;

        s_xyz[3 * t + 0] = rx;            // self-overwrite, no hazard
        s_xyz[3 * t + 1] = ry;
        s_xyz[3 * t + 2] = rz;

        d = sqrtf(rx * rx + ry * ry + rz * rz);
        __stcs(&out_dist[i], d);
    }

    // fused centroid output (covers gid < n_blocks; n_blocks << n_atoms)
    {
        int gid = a0 + t;
        if (gid < n_blocks) {
            float4 s = g_sums[gid];
            float inv = 1.f / fmaxf(s.w, 1.f);
            out_cent[3 * gid + 0] = s.x * inv;
            out_cent[3 * gid + 1] = s.y * inv;
            out_cent[3 * gid + 2] = s.z * inv;
        }
    }
    __syncthreads();

    // ---- cooperative rel store ----
    if (fullt) {
        float4* r4 = (float4*)(out_rel + (size_t)3 * a0);
        if (t < (3 * TPB / 4)) __stcs(&r4[t], ((const float4*)s_xyz)[t]);
    } else {
        for (int k = t; k < 3 * TPB; k += TPB) {
            int gi = 3 * a0 + k;
            if (gi < 3 * n_atoms) out_rel[gi] = s_xyz[k];
        }
    }

    // ---- transposed rbf stores ----
    int wbase = a0 + (t & ~31);
    int sub   = lane >> 2;                // 0..7: atom within the round's 8
#pragma unroll
    for (int r = 0; r < 4; ++r) {
        int src_lane = 8 * r + sub;
        float dd = __shfl_sync(0xffffffffu, d, src_lane);
        int atom = wbase + 8 * r + sub;
        if (atom < n_atoms) {
            float d2 = dd * dd;
            float4 v;
            v.x = exp2f(fmaf(d2, A0, fmaf(dd, B0, C0)));
            v.y = exp2f(fmaf(d2, A1, fmaf(dd, B1, C1)));
            v.z = exp2f(fmaf(d2, A2, fmaf(dd, B2, C2)));
            v.w = exp2f(fmaf(d2, A3, fmaf(dd, B3, C3)));
            __stcs(&out_rbf[(size_t)atom * 4 + q], v);
        }
    }
}

static inline int clamp_grid(long long b) {
    if (b < 1) return 1;
    if (b > 1048576) return 1048576;
    return (int)b;
}

extern "C" void kernel_launch(void* const* d_in, const int* in_sizes, int n_in,
                              void* d_out, int out_size) {
    const float* pos     = (const float*)d_in[0];  // [n_atoms*3]
    const int*   bid     = (const int*)d_in[1];    // [n_atoms]
    // d_in[2] = n_blocks scalar on device; derive arithmetically (no sync copies)
    const float* centers = (const float*)d_in[3];  // [16]
    const float* widths  = (const float*)d_in[4];  // [16]

    int n_atoms  = in_sizes[0] / 3;
    long long nb = ((long long)out_size - (long long)n_atoms * (3 + 1 + RBF_DIM)) / 3;
    int n_blocks = (int)nb;
    if (n_blocks < 1) n_blocks = 1;
    if (n_blocks > MAX_BLOCKS_SCRATCH) n_blocks = MAX_BLOCKS_SCRATCH;

    float* out      = (float*)d_out;
    float* out_cent = out;                                    // n_blocks*3
    float* out_rel  = out + (size_t)n_blocks * 3;             // n_atoms*3
    float* out_dist = out_rel + (size_t)n_atoms * 3;          // n_atoms
    float4* out_rbf = (float4*)(out_dist + (size_t)n_atoms);  // n_atoms*16 floats

    // 1) zero scratch
    k_zero_sums<<<clamp_grid((n_blocks + 255) / 256), 256>>>(n_blocks);

    // 2) segment sums (flat, staged loads, warp-aggregated atomics)
    if (n_atoms > 0)
        k_accum<<<clamp_grid(((long long)n_atoms + TPB - 1) / TPB), TPB>>>(pos, bid, n_atoms);

    // 3) per-atom rel/dist/rbf + fused centroid output
    if (n_atoms > 0)
        k_atoms<<<clamp_grid(((long long)n_atoms + TPB - 1) / TPB), TPB>>>(
            pos, bid, centers, widths, out_cent, out_rel, out_dist, out_rbf,
            n_atoms, n_blocks);
}

// round 12
// speedup vs baseline: 1.0201x; 1.0201x over previous
#include <cuda_runtime.h>

// ---------------------------------------------------------------------------
// BatchedGeometryComputation
//   out = [centroids (n_blocks*3) | rel (n_atoms*3) | dist (n_atoms) | rbf (n_atoms*16)]
// block_id is SORTED ascending.
// ---------------------------------------------------------------------------

#define RBF_DIM 16
#define MAX_BLOCKS_SCRATCH 262144
#define TPB 256
#define LOG2E 1.4426950408889634f

// raw MUFU exp2 (the harness does not enable fast-math; exp2f() would lower
// to the slow accurate path, __expf-style intrinsics use this unit directly)
__device__ __forceinline__ float ex2_approx(float x) {
    float y;
    asm("ex2.approx.ftz.f32 %0, %1;" : "=f"(y) : "f"(x));
    return y;
}

// scratch: per-block (sum_x, sum_y, sum_z, count)
__device__ float4 g_sums[MAX_BLOCKS_SCRATCH];

__global__ void k_zero_sums(int n_blocks) {
    for (int i = blockIdx.x * blockDim.x + threadIdx.x; i < n_blocks;
         i += gridDim.x * blockDim.x)
        g_sums[i] = make_float4(0.f, 0.f, 0.f, 0.f);
}

// One atom per lane; pos staged via float4 into shared (3 load wf/warp);
// warp-level segmented reduction over sorted ids; heads issue atomics.
__global__ void __launch_bounds__(TPB)
k_accum(const float* __restrict__ pos,
        const int* __restrict__ bid,
        int n_atoms) {
    __shared__ float s_p[3 * TPB];
    int t    = threadIdx.x;
    int lane = t & 31;
    int a0   = blockIdx.x * TPB;
    bool fullt = (a0 + TPB) <= n_atoms;

    if (fullt) {
        const float4* p4 = (const float4*)(pos + (size_t)3 * a0);
        if (t < (3 * TPB / 4)) ((float4*)s_p)[t] = p4[t];
    } else {
        for (int k = t; k < 3 * TPB; k += TPB) {
            int gi = 3 * a0 + k;
            s_p[k] = (gi < 3 * n_atoms) ? pos[gi] : 0.f;
        }
    }
    __syncthreads();

    int i = a0 + t;
    bool valid = i < n_atoms;
    int idx = valid ? i : (n_atoms - 1);

    int   b   = bid[idx];
    float sx  = valid ? s_p[3 * t + 0] : 0.f;
    float sy  = valid ? s_p[3 * t + 1] : 0.f;
    float sz  = valid ? s_p[3 * t + 2] : 0.f;
    float cnt = valid ? 1.f : 0.f;

#pragma unroll
    for (int off = 1; off < 32; off <<= 1) {
        int   ob = __shfl_down_sync(0xffffffffu, b, off);
        float ox = __shfl_down_sync(0xffffffffu, sx, off);
        float oy = __shfl_down_sync(0xffffffffu, sy, off);
        float oz = __shfl_down_sync(0xffffffffu, sz, off);
        float oc = __shfl_down_sync(0xffffffffu, cnt, off);
        if (lane + off < 32 && ob == b) {
            sx += ox; sy += oy; sz += oz; cnt += oc;
        }
    }

    int prev_b = __shfl_up_sync(0xffffffffu, b, 1);
    bool head = (lane == 0) || (prev_b != b);
    if (head && cnt > 0.f) {
        float* p = (float*)&g_sums[b];
        atomicAdd(p + 0, sx);
        atomicAdd(p + 1, sy);
        atomicAdd(p + 2, sz);
        atomicAdd(p + 3, cnt);
    }
}

// Per-atom kernel, transposed rbf stores, FMA-form exp args lowered to raw
// EX2, fused centroid output.
__global__ void __launch_bounds__(TPB, 6)
k_atoms(const float* __restrict__ pos,
        const int* __restrict__ bid,
        const float* __restrict__ centers,
        const float* __restrict__ widths,
        float* __restrict__ out_cent,
        float* __restrict__ out_rel,
        float* __restrict__ out_dist,
        float4* __restrict__ out_rbf,     // n_atoms * 4 float4
        int n_atoms, int n_blocks) {
    __shared__ float s_c[RBF_DIM];
    __shared__ float s_iw[RBF_DIM];
    __shared__ float s_xyz[3 * TPB];      // staged pos, then reused for rel

    int t    = threadIdx.x;
    int lane = t & 31;

    if (t < RBF_DIM) {
        s_c[t] = centers[t];
        float w = widths[t];
        s_iw[t] = 1.f / (2.f * w * w);
    }

    int a0 = blockIdx.x * TPB;            // first atom of this block
    bool fullt = (a0 + TPB) <= n_atoms;

    // ---- stage pos into shared ----
    if (fullt) {
        const float4* p4 = (const float4*)(pos + (size_t)3 * a0);
        if (t < (3 * TPB / 4)) ((float4*)s_xyz)[t] = p4[t];
    } else {
        for (int k = t; k < 3 * TPB; k += TPB) {
            int gi = 3 * a0 + k;
            s_xyz[k] = (gi < 3 * n_atoms) ? pos[gi] : 0.f;
        }
    }
    __syncthreads();

    // per-lane RBF constants in FMA form:
    //   exp(-(d-c)^2*iw) = exp2(A*d^2 + B*d + C)
    int q = lane & 3;
    float A0, A1, A2, A3, B0, B1, B2, B3, C0, C1, C2, C3;
    {
        float c, iw, il;
        c = s_c[4 * q + 0]; iw = s_iw[4 * q + 0]; il = iw * LOG2E;
        A0 = -il; B0 = 2.f * c * il; C0 = -c * c * il;
        c = s_c[4 * q + 1]; iw = s_iw[4 * q + 1]; il = iw * LOG2E;
        A1 = -il; B1 = 2.f * c * il; C1 = -c * c * il;
        c = s_c[4 * q + 2]; iw = s_iw[4 * q + 2]; il = iw * LOG2E;
        A2 = -il; B2 = 2.f * c * il; C2 = -c * c * il;
        c = s_c[4 * q + 3]; iw = s_iw[4 * q + 3]; il = iw * LOG2E;
        A3 = -il; B3 = 2.f * c * il; C3 = -c * c * il;
    }

    int i = a0 + t;
    bool act = i < n_atoms;
    float d = 0.f;

    if (act) {
        int b = bid[i];
        float4 s = g_sums[b];             // single LDG.128, broadcast-friendly
        float inv = 1.f / fmaxf(s.w, 1.f);

        float rx = s_xyz[3 * t + 0] - s.x * inv;
        float ry = s_xyz[3 * t + 1] - s.y * inv;
        float rz = s_xyz[3 * t + 2] - s.z * inv;

        s_xyz[3 * t + 0] = rx;            // self-overwrite, no hazard
        s_xyz[3 * t + 1] = ry;
        s_xyz[3 * t + 2] = rz;

        d = sqrtf(rx * rx + ry * ry + rz * rz);
        __stcs(&out_dist[i], d);
    }

    // fused centroid output (covers gid < n_blocks; n_blocks << n_atoms)
    {
        int gid = a0 + t;
        if (gid < n_blocks) {
            float4 s = g_sums[gid];
            float inv = 1.f / fmaxf(s.w, 1.f);
            out_cent[3 * gid + 0] = s.x * inv;
            out_cent[3 * gid + 1] = s.y * inv;
            out_cent[3 * gid + 2] = s.z * inv;
        }
    }
    __syncthreads();

    // ---- cooperative rel store ----
    if (fullt) {
        float4* r4 = (float4*)(out_rel + (size_t)3 * a0);
        if (t < (3 * TPB / 4)) __stcs(&r4[t], ((const float4*)s_xyz)[t]);
    } else {
        for (int k = t; k < 3 * TPB; k += TPB) {
            int gi = 3 * a0 + k;
            if (gi < 3 * n_atoms) out_rel[gi] = s_xyz[k];
        }
    }

    // ---- transposed rbf stores ----
    int wbase = a0 + (t & ~31);
    int sub   = lane >> 2;                // 0..7: atom within the round's 8
#pragma unroll
    for (int r = 0; r < 4; ++r) {
        int src_lane = 8 * r + sub;
        float dd = __shfl_sync(0xffffffffu, d, src_lane);
        int atom = wbase + 8 * r + sub;
        if (atom < n_atoms) {
            float d2 = dd * dd;
            float4 v;
            v.x = ex2_approx(fmaf(d2, A0, fmaf(dd, B0, C0)));
            v.y = ex2_approx(fmaf(d2, A1, fmaf(dd, B1, C1)));
            v.z = ex2_approx(fmaf(d2, A2, fmaf(dd, B2, C2)));
            v.w = ex2_approx(fmaf(d2, A3, fmaf(dd, B3, C3)));
            __stcs(&out_rbf[(size_t)atom * 4 + q], v);
        }
    }
}

static inline int clamp_grid(long long b) {
    if (b < 1) return 1;
    if (b > 1048576) return 1048576;
    return (int)b;
}

extern "C" void kernel_launch(void* const* d_in, const int* in_sizes, int n_in,
                              void* d_out, int out_size) {
    const float* pos     = (const float*)d_in[0];  // [n_atoms*3]
    const int*   bid     = (const int*)d_in[1];    // [n_atoms]
    // d_in[2] = n_blocks scalar on device; derive arithmetically (no sync copies)
    const float* centers = (const float*)d_in[3];  // [16]
    const float* widths  = (const float*)d_in[4];  // [16]

    int n_atoms  = in_sizes[0] / 3;
    long long nb = ((long long)out_size - (long long)n_atoms * (3 + 1 + RBF_DIM)) / 3;
    int n_blocks = (int)nb;
    if (n_blocks < 1) n_blocks = 1;
    if (n_blocks > MAX_BLOCKS_SCRATCH) n_blocks = MAX_BLOCKS_SCRATCH;

    float* out      = (float*)d_out;
    float* out_cent = out;                                    // n_blocks*3
    float* out_rel  = out + (size_t)n_blocks * 3;             // n_atoms*3
    float* out_dist = out_rel + (size_t)n_atoms * 3;          // n_atoms
    float4* out_rbf = (float4*)(out_dist + (size_t)n_atoms);  // n_atoms*16 floats

    // 1) zero scratch
    k_zero_sums<<<clamp_grid((n_blocks + 255) / 256), 256>>>(n_blocks);

    // 2) segment sums (flat, staged loads, warp-aggregated atomics)
    if (n_atoms > 0)
        k_accum<<<clamp_grid(((long long)n_atoms + TPB - 1) / TPB), TPB>>>(pos, bid, n_atoms);

    // 3) per-atom rel/dist/rbf + fused centroid output
    if (n_atoms > 0)
        k_atoms<<<clamp_grid(((long long)n_atoms + TPB - 1) / TPB), TPB>>>(
            pos, bid, centers, widths, out_cent, out_rel, out_dist, out_rbf,
            n_atoms, n_blocks);
}

// round 13
// speedup vs baseline: 1.0611x; 1.0402x over previous
#include <cuda_runtime.h>

// ---------------------------------------------------------------------------
// BatchedGeometryComputation
//   out = [centroids (n_blocks*3) | rel (n_atoms*3) | dist (n_atoms) | rbf (n_atoms*16)]
// block_id is SORTED ascending.
// R13 = R9 (best: 94.2us) + FMA-form EX2 rbf only. No other changes.
// ---------------------------------------------------------------------------

#define RBF_DIM 16
#define MAX_BLOCKS_SCRATCH 262144
#define TPB 256
#define LOG2E 1.4426950408889634f

// raw MUFU exp2 (harness does not enable fast-math; exp2f() lowers to the
// slow accurate path)
__device__ __forceinline__ float ex2_approx(float x) {
    float y;
    asm("ex2.approx.ftz.f32 %0, %1;" : "=f"(y) : "f"(x));
    return y;
}

// scratch: per-block (sum_x, sum_y, sum_z, count)
__device__ float4 g_sums[MAX_BLOCKS_SCRATCH];

__global__ void k_zero_sums(int n_blocks) {
    for (int i = blockIdx.x * blockDim.x + threadIdx.x; i < n_blocks;
         i += gridDim.x * blockDim.x)
        g_sums[i] = make_float4(0.f, 0.f, 0.f, 0.f);
}

// One atom per lane (coalesced). Warp-level segmented reduction over the
// sorted block ids; only segment heads issue atomics.  (R9 flat version.)
__global__ void k_accum(const float* __restrict__ pos,
                        const int* __restrict__ bid,
                        int n_atoms) {
    int i    = blockIdx.x * blockDim.x + threadIdx.x;
    int lane = threadIdx.x & 31;

    bool valid = i < n_atoms;
    int idx = valid ? i : (n_atoms - 1);

    int   b   = bid[idx];
    float sx  = valid ? pos[3 * idx + 0] : 0.f;
    float sy  = valid ? pos[3 * idx + 1] : 0.f;
    float sz  = valid ? pos[3 * idx + 2] : 0.f;
    float cnt = valid ? 1.f : 0.f;

#pragma unroll
    for (int off = 1; off < 32; off <<= 1) {
        int   ob = __shfl_down_sync(0xffffffffu, b, off);
        float ox = __shfl_down_sync(0xffffffffu, sx, off);
        float oy = __shfl_down_sync(0xffffffffu, sy, off);
        float oz = __shfl_down_sync(0xffffffffu, sz, off);
        float oc = __shfl_down_sync(0xffffffffu, cnt, off);
        if (lane + off < 32 && ob == b) {
            sx += ox; sy += oy; sz += oz; cnt += oc;
        }
    }

    int prev_b = __shfl_up_sync(0xffffffffu, b, 1);
    bool head = (lane == 0) || (prev_b != b);
    if (head && cnt > 0.f) {
        float* p = (float*)&g_sums[b];
        atomicAdd(p + 0, sx);
        atomicAdd(p + 1, sy);
        atomicAdd(p + 2, sz);
        atomicAdd(p + 3, cnt);
    }
}

__global__ void k_centroid(float* __restrict__ out_c, int n_blocks) {
    for (int i = blockIdx.x * blockDim.x + threadIdx.x; i < n_blocks;
         i += gridDim.x * blockDim.x) {
        float4 s = g_sums[i];
        float inv = 1.f / fmaxf(s.w, 1.f);
        out_c[3 * i + 0] = s.x * inv;
        out_c[3 * i + 1] = s.y * inv;
        out_c[3 * i + 2] = s.z * inv;
    }
}

// Per-atom kernel with TRANSPOSED rbf stores (R9 skeleton).
//  - pos staged cooperatively as float4 into shared
//  - rel computed per-atom, written back to shared, stored coop as float4
//  - dist stored per-atom
//  - rbf: 4 rounds/warp; lane L handles atom (w0+8r+L/4), k-quarter q=L%3
//    -> STG.128 covering 512 contiguous bytes. d redistributed via shfl.
//  - ONLY change vs R9: exp arg in FMA form  exp2(A*d^2 + B*d + C), raw EX2.
__global__ void __launch_bounds__(TPB, 6)
k_atoms(const float* __restrict__ pos,
        const int* __restrict__ bid,
        const float* __restrict__ centers,
        const float* __restrict__ widths,
        float* __restrict__ out_rel,
        float* __restrict__ out_dist,
        float4* __restrict__ out_rbf,     // n_atoms * 4 float4
        int n_atoms) {
    __shared__ float s_c[RBF_DIM];
    __shared__ float s_iw[RBF_DIM];
    __shared__ float s_xyz[3 * TPB];      // staged pos, then reused for rel

    int t    = threadIdx.x;
    int lane = t & 31;

    if (t < RBF_DIM) {
        s_c[t] = centers[t];
        float w = widths[t];
        s_iw[t] = 1.f / (2.f * w * w);
    }

    int a0 = blockIdx.x * TPB;            // first atom of this block
    bool fullt = (a0 + TPB) <= n_atoms;

    // ---- stage pos into shared ----
    if (fullt) {
        const float4* p4 = (const float4*)(pos + (size_t)3 * a0);
        if (t < (3 * TPB / 4)) ((float4*)s_xyz)[t] = p4[t];
    } else {
        for (int k = t; k < 3 * TPB; k += TPB) {
            int gi = 3 * a0 + k;
            s_xyz[k] = (gi < 3 * n_atoms) ? pos[gi] : 0.f;
        }
    }
    __syncthreads();

    // per-lane RBF constants in FMA form (q = lane & 3 fixed per thread):
    //   exp(-(d-c)^2*iw) = exp2(A*d^2 + B*d + C)
    int q = lane & 3;
    float A0, A1, A2, A3, B0, B1, B2, B3, C0, C1, C2, C3;
    {
        float c, iw, il;
        c = s_c[4 * q + 0]; iw = s_iw[4 * q + 0]; il = iw * LOG2E;
        A0 = -il; B0 = 2.f * c * il; C0 = -c * c * il;
        c = s_c[4 * q + 1]; iw = s_iw[4 * q + 1]; il = iw * LOG2E;
        A1 = -il; B1 = 2.f * c * il; C1 = -c * c * il;
        c = s_c[4 * q + 2]; iw = s_iw[4 * q + 2]; il = iw * LOG2E;
        A2 = -il; B2 = 2.f * c * il; C2 = -c * c * il;
        c = s_c[4 * q + 3]; iw = s_iw[4 * q + 3]; il = iw * LOG2E;
        A3 = -il; B3 = 2.f * c * il; C3 = -c * c * il;
    }

    int i = a0 + t;
    bool act = i < n_atoms;
    float d = 0.f;

    if (act) {
        int b = bid[i];
        float4 s = g_sums[b];             // single LDG.128, broadcast-friendly
        float inv = 1.f / fmaxf(s.w, 1.f);

        float rx = s_xyz[3 * t + 0] - s.x * inv;
        float ry = s_xyz[3 * t + 1] - s.y * inv;
        float rz = s_xyz[3 * t + 2] - s.z * inv;

        s_xyz[3 * t + 0] = rx;            // self-overwrite, no hazard
        s_xyz[3 * t + 1] = ry;
        s_xyz[3 * t + 2] = rz;

        d = sqrtf(rx * rx + ry * ry + rz * rz);
        __stcs(&out_dist[i], d);
    }
    __syncthreads();

    // ---- cooperative rel store ----
    if (fullt) {
        float4* r4 = (float4*)(out_rel + (size_t)3 * a0);
        if (t < (3 * TPB / 4)) __stcs(&r4[t], ((const float4*)s_xyz)[t]);
    } else {
        for (int k = t; k < 3 * TPB; k += TPB) {
            int gi = 3 * a0 + k;
            if (gi < 3 * n_atoms) out_rel[gi] = s_xyz[k];
        }
    }

    // ---- transposed rbf stores ----
    int wbase = a0 + (t & ~31);
    int sub   = lane >> 2;                // 0..7: atom within the round's 8
#pragma unroll
    for (int r = 0; r < 4; ++r) {
        int src_lane = 8 * r + sub;
        float dd = __shfl_sync(0xffffffffu, d, src_lane);
        int atom = wbase + 8 * r + sub;
        if (atom < n_atoms) {
            float d2 = dd * dd;
            float4 v;
            v.x = ex2_approx(fmaf(d2, A0, fmaf(dd, B0, C0)));
            v.y = ex2_approx(fmaf(d2, A1, fmaf(dd, B1, C1)));
            v.z = ex2_approx(fmaf(d2, A2, fmaf(dd, B2, C2)));
            v.w = ex2_approx(fmaf(d2, A3, fmaf(dd, B3, C3)));
            __stcs(&out_rbf[(size_t)atom * 4 + q], v);
        }
    }
}

static inline int clamp_grid(long long b) {
    if (b < 1) return 1;
    if (b > 1048576) return 1048576;
    return (int)b;
}

extern "C" void kernel_launch(void* const* d_in, const int* in_sizes, int n_in,
                              void* d_out, int out_size) {
    const float* pos     = (const float*)d_in[0];  // [n_atoms*3]
    const int*   bid     = (const int*)d_in[1];    // [n_atoms]
    // d_in[2] = n_blocks scalar on device; derive arithmetically (no sync copies)
    const float* centers = (const float*)d_in[3];  // [16]
    const float* widths  = (const float*)d_in[4];  // [16]

    int n_atoms  = in_sizes[0] / 3;
    long long nb = ((long long)out_size - (long long)n_atoms * (3 + 1 + RBF_DIM)) / 3;
    int n_blocks = (int)nb;
    if (n_blocks < 1) n_blocks = 1;
    if (n_blocks > MAX_BLOCKS_SCRATCH) n_blocks = MAX_BLOCKS_SCRATCH;

    float* out      = (float*)d_out;
    float* out_cent = out;                                    // n_blocks*3
    float* out_rel  = out + (size_t)n_blocks * 3;             // n_atoms*3
    float* out_dist = out_rel + (size_t)n_atoms * 3;          // n_atoms
    float4* out_rbf = (float4*)(out_dist + (size_t)n_atoms);  // n_atoms*16 floats

    // 1) zero scratch
    k_zero_sums<<<clamp_grid((n_blocks + 255) / 256), 256>>>(n_blocks);

    // 2) segment sums (flat, coalesced, warp-aggregated atomics)
    if (n_atoms > 0)
        k_accum<<<clamp_grid(((long long)n_atoms + 255) / 256), 256>>>(pos, bid, n_atoms);

    // 3) centroids output
    k_centroid<<<clamp_grid((n_blocks + 255) / 256), 256>>>(out_cent, n_blocks);

    // 4) per-atom rel/dist/rbf (flat grid; reads g_sums directly)
    if (n_atoms > 0)
        k_atoms<<<clamp_grid(((long long)n_atoms + TPB - 1) / TPB), TPB>>>(
            pos, bid, centers, widths, out_rel, out_dist, out_rbf, n_atoms);
}

// round 14
// speedup vs baseline: 1.1903x; 1.1218x over previous
#include <cuda_runtime.h>

// ---------------------------------------------------------------------------
// BatchedGeometryComputation
//   out = [centroids (n_blocks*3) | rel (n_atoms*3) | dist (n_atoms) | rbf (n_atoms*16)]
// block_id is SORTED ascending.
// R14 = R9 skeleton + 4-instr exp (8 consts, occupancy-neutral)
//       + approx sqrt/rcp + centroid fused into k_atoms.
// ---------------------------------------------------------------------------

#define RBF_DIM 16
#define MAX_BLOCKS_SCRATCH 262144
#define TPB 256
#define LOG2E 1.4426950408889634f

// raw MUFU ops (harness does not enable fast-math; library forms lower to
// slow accurate sequences)
__device__ __forceinline__ float ex2_approx(float x) {
    float y; asm("ex2.approx.ftz.f32 %0, %1;" : "=f"(y) : "f"(x)); return y;
}
__device__ __forceinline__ float sqrt_approx(float x) {
    float y; asm("sqrt.approx.ftz.f32 %0, %1;" : "=f"(y) : "f"(x)); return y;
}
__device__ __forceinline__ float rcp_approx(float x) {
    float y; asm("rcp.approx.ftz.f32 %0, %1;" : "=f"(y) : "f"(x)); return y;
}

// scratch: per-block (sum_x, sum_y, sum_z, count)
__device__ float4 g_sums[MAX_BLOCKS_SCRATCH];

__global__ void k_zero_sums(int n_blocks) {
    for (int i = blockIdx.x * blockDim.x + threadIdx.x; i < n_blocks;
         i += gridDim.x * blockDim.x)
        g_sums[i] = make_float4(0.f, 0.f, 0.f, 0.f);
}

// One atom per lane (coalesced). Warp-level segmented reduction over the
// sorted block ids; only segment heads issue atomics.  (R9 flat version.)
__global__ void k_accum(const float* __restrict__ pos,
                        const int* __restrict__ bid,
                        int n_atoms) {
    int i    = blockIdx.x * blockDim.x + threadIdx.x;
    int lane = threadIdx.x & 31;

    bool valid = i < n_atoms;
    int idx = valid ? i : (n_atoms - 1);

    int   b   = bid[idx];
    float sx  = valid ? pos[3 * idx + 0] : 0.f;
    float sy  = valid ? pos[3 * idx + 1] : 0.f;
    float sz  = valid ? pos[3 * idx + 2] : 0.f;
    float cnt = valid ? 1.f : 0.f;

#pragma unroll
    for (int off = 1; off < 32; off <<= 1) {
        int   ob = __shfl_down_sync(0xffffffffu, b, off);
        float ox = __shfl_down_sync(0xffffffffu, sx, off);
        float oy = __shfl_down_sync(0xffffffffu, sy, off);
        float oz = __shfl_down_sync(0xffffffffu, sz, off);
        float oc = __shfl_down_sync(0xffffffffu, cnt, off);
        if (lane + off < 32 && ob == b) {
            sx += ox; sy += oy; sz += oz; cnt += oc;
        }
    }

    int prev_b = __shfl_up_sync(0xffffffffu, b, 1);
    bool head = (lane == 0) || (prev_b != b);
    if (head && cnt > 0.f) {
        float* p = (float*)&g_sums[b];
        atomicAdd(p + 0, sx);
        atomicAdd(p + 1, sy);
        atomicAdd(p + 2, sz);
        atomicAdd(p + 3, cnt);
    }
}

// Per-atom kernel with TRANSPOSED rbf stores (R9 skeleton) + fused centroid.
//  - pos staged cooperatively as float4 into shared
//  - rel computed per-atom, written back to shared, stored coop as float4
//  - dist stored per-atom
//  - rbf: 4 rounds/warp; lane L handles atom (wbase+8r+L/4), k-quarter
//    q=L&3 -> STG.128 covering 512 contiguous bytes; d moved via shfl
//  - exp: u=d-c; ex2(A*u*u), A=-iw*log2e  (4 instr, 8 const regs)
//  - approx sqrt/rcp (1 MUFU each)
//  - threads with gid < n_blocks also emit centroids from g_sums
__global__ void __launch_bounds__(TPB, 6)
k_atoms(const float* __restrict__ pos,
        const int* __restrict__ bid,
        const float* __restrict__ centers,
        const float* __restrict__ widths,
        float* __restrict__ out_cent,
        float* __restrict__ out_rel,
        float* __restrict__ out_dist,
        float4* __restrict__ out_rbf,     // n_atoms * 4 float4
        int n_atoms, int n_blocks) {
    __shared__ float s_c[RBF_DIM];
    __shared__ float s_iw[RBF_DIM];
    __shared__ float s_xyz[3 * TPB];      // staged pos, then reused for rel

    int t    = threadIdx.x;
    int lane = t & 31;

    if (t < RBF_DIM) {
        s_c[t] = centers[t];
        float w = widths[t];
        s_iw[t] = 1.f / (2.f * w * w);
    }

    int a0 = blockIdx.x * TPB;            // first atom of this block
    bool fullt = (a0 + TPB) <= n_atoms;

    // ---- stage pos into shared ----
    if (fullt) {
        const float4* p4 = (const float4*)(pos + (size_t)3 * a0);
        if (t < (3 * TPB / 4)) ((float4*)s_xyz)[t] = p4[t];
    } else {
        for (int k = t; k < 3 * TPB; k += TPB) {
            int gi = 3 * a0 + k;
            s_xyz[k] = (gi < 3 * n_atoms) ? pos[gi] : 0.f;
        }
    }
    __syncthreads();

    // per-lane RBF constants (q = lane & 3 fixed per thread):
    //   exp(-(d-c)^2*iw) = ex2(A*(d-c)^2),  A = -iw*log2e
    int q = lane & 3;
    float c0 = s_c[4 * q + 0], c1 = s_c[4 * q + 1];
    float c2 = s_c[4 * q + 2], c3 = s_c[4 * q + 3];
    float A0 = -s_iw[4 * q + 0] * LOG2E, A1 = -s_iw[4 * q + 1] * LOG2E;
    float A2 = -s_iw[4 * q + 2] * LOG2E, A3 = -s_iw[4 * q + 3] * LOG2E;

    int i = a0 + t;
    bool act = i < n_atoms;
    float d = 0.f;

    if (act) {
        int b = bid[i];
        float4 s = g_sums[b];             // single LDG.128, broadcast-friendly
        float inv = rcp_approx(fmaxf(s.w, 1.f));

        float rx = s_xyz[3 * t + 0] - s.x * inv;
        float ry = s_xyz[3 * t + 1] - s.y * inv;
        float rz = s_xyz[3 * t + 2] - s.z * inv;

        s_xyz[3 * t + 0] = rx;            // self-overwrite, no hazard
        s_xyz[3 * t + 1] = ry;
        s_xyz[3 * t + 2] = rz;

        d = sqrt_approx(fmaf(rx, rx, fmaf(ry, ry, rz * rz)));
        __stcs(&out_dist[i], d);
    }

    // fused centroid output (gid < n_blocks; n_blocks << n_atoms)
    {
        int gid = a0 + t;
        if (gid < n_blocks) {
            float4 s = g_sums[gid];
            float inv = rcp_approx(fmaxf(s.w, 1.f));
            out_cent[3 * gid + 0] = s.x * inv;
            out_cent[3 * gid + 1] = s.y * inv;
            out_cent[3 * gid + 2] = s.z * inv;
        }
    }
    __syncthreads();

    // ---- cooperative rel store ----
    if (fullt) {
        float4* r4 = (float4*)(out_rel + (size_t)3 * a0);
        if (t < (3 * TPB / 4)) __stcs(&r4[t], ((const float4*)s_xyz)[t]);
    } else {
        for (int k = t; k < 3 * TPB; k += TPB) {
            int gi = 3 * a0 + k;
            if (gi < 3 * n_atoms) out_rel[gi] = s_xyz[k];
        }
    }

    // ---- transposed rbf stores ----
    int wbase = a0 + (t & ~31);
    int sub   = lane >> 2;                // 0..7: atom within the round's 8
#pragma unroll
    for (int r = 0; r < 4; ++r) {
        int src_lane = 8 * r + sub;
        float dd = __shfl_sync(0xffffffffu, d, src_lane);
        int atom = wbase + 8 * r + sub;
        if (atom < n_atoms) {
            float u;
            float4 v;
            u = dd - c0; v.x = ex2_approx((A0 * u) * u);
            u = dd - c1; v.y = ex2_approx((A1 * u) * u);
            u = dd - c2; v.z = ex2_approx((A2 * u) * u);
            u = dd - c3; v.w = ex2_approx((A3 * u) * u);
            __stcs(&out_rbf[(size_t)atom * 4 + q], v);
        }
    }
}

static inline int clamp_grid(long long b) {
    if (b < 1) return 1;
    if (b > 1048576) return 1048576;
    return (int)b;
}

extern "C" void kernel_launch(void* const* d_in, const int* in_sizes, int n_in,
                              void* d_out, int out_size) {
    const float* pos     = (const float*)d_in[0];  // [n_atoms*3]
    const int*   bid     = (const int*)d_in[1];    // [n_atoms]
    // d_in[2] = n_blocks scalar on device; derive arithmetically (no sync copies)
    const float* centers = (const float*)d_in[3];  // [16]
    const float* widths  = (const float*)d_in[4];  // [16]

    int n_atoms  = in_sizes[0] / 3;
    long long nb = ((long long)out_size - (long long)n_atoms * (3 + 1 + RBF_DIM)) / 3;
    int n_blocks = (int)nb;
    if (n_blocks < 1) n_blocks = 1;
    if (n_blocks > MAX_BLOCKS_SCRATCH) n_blocks = MAX_BLOCKS_SCRATCH;

    float* out      = (float*)d_out;
    float* out_cent = out;                                    // n_blocks*3
    float* out_rel  = out + (size_t)n_blocks * 3;             // n_atoms*3
    float* out_dist = out_rel + (size_t)n_atoms * 3;          // n_atoms
    float4* out_rbf = (float4*)(out_dist + (size_t)n_atoms);  // n_atoms*16 floats

    // 1) zero scratch
    k_zero_sums<<<clamp_grid((n_blocks + 255) / 256), 256>>>(n_blocks);

    // 2) segment sums (flat, coalesced, warp-aggregated atomics)
    if (n_atoms > 0)
        k_accum<<<clamp_grid(((long long)n_atoms + 255) / 256), 256>>>(pos, bid, n_atoms);

    // 3) per-atom rel/dist/rbf + fused centroid output
    if (n_atoms > 0)
        k_atoms<<<clamp_grid(((long long)n_atoms + TPB - 1) / TPB), TPB>>>(
            pos, bid, centers, widths, out_cent, out_rel, out_dist, out_rbf,
            n_atoms, n_blocks);
}